// round 1
// baseline (speedup 1.0000x reference)
#include <cuda_runtime.h>

// Problem constants (fixed shapes from reference)
#define BATCH   2
#define NPTS    2048
#define CIN     64
#define COUT    128
#define GRIDV   12
#define NVOX    (GRIDV*GRIDV*GRIDV)   // 1728
#define NOFF    27
#define TM      32                    // points per conv block

// Scratch: per-voxel aggregated features (fp32), zeroed every launch
__device__ float g_aggF[BATCH * NVOX * CIN];

// ---------------------------------------------------------------------------
// Kernel 1: zero the aggregation scratch
// ---------------------------------------------------------------------------
__global__ void zero_agg_kernel() {
    int i = blockIdx.x * blockDim.x + threadIdx.x;
    const int total4 = BATCH * NVOX * CIN / 4;
    if (i < total4) {
        ((float4*)g_aggF)[i] = make_float4(0.f, 0.f, 0.f, 0.f);
    }
}

// ---------------------------------------------------------------------------
// Kernel 2: scatter-add features into per-voxel bins
// one thread per (point, channel)
// ---------------------------------------------------------------------------
__global__ void aggregate_kernel(const float* __restrict__ points,
                                 const float* __restrict__ feats) {
    int gid = blockIdx.x * blockDim.x + threadIdx.x;
    if (gid >= BATCH * NPTS * CIN) return;
    int c = gid & (CIN - 1);
    int p = gid >> 6;                 // global point index 0..B*N-1
    int b = p / NPTS;
    // truncation toward zero == reference astype(int32); points are positive
    int vx = (int)points[p * 3 + 0];
    int vy = (int)points[p * 3 + 1];
    int vz = (int)points[p * 3 + 2];
    if ((unsigned)vx >= GRIDV || (unsigned)vy >= GRIDV || (unsigned)vz >= GRIDV) return;
    int lin = (vx * GRIDV + vy) * GRIDV + vz;
    atomicAdd(&g_aggF[(b * NVOX + lin) * CIN + c], feats[gid]);
}

// ---------------------------------------------------------------------------
// Kernel 3: per-point conv: out[p] = sum_o aggF[vox[p]+off(o)] @ W[o] + bias
// Block: TM=32 points x full COUT=128. 256 threads.
// Thread (tx=tid&15, ty=tid>>4): computes points {2ty, 2ty+1} x couts [8tx, 8tx+8)
// ---------------------------------------------------------------------------
__global__ __launch_bounds__(256, 1)
void conv_kernel(const float* __restrict__ points,
                 const float* __restrict__ weight,
                 const float* __restrict__ bias,
                 float* __restrict__ out) {
    __shared__ float Ws[CIN][COUT];        // 32 KB: weight slice for current offset
    __shared__ float As[TM][CIN + 4];      // ~8.7 KB: gathered neighbor aggregates (padded)
    __shared__ int   svx[TM], svy[TM], svz[TM];

    const int tid  = threadIdx.x;
    const int tile = blockIdx.x;            // 0 .. B*N/TM - 1
    const int p0   = tile * TM;             // tile never crosses batch (2048 % 32 == 0)
    const int b    = p0 / NPTS;

    if (tid < TM) {
        int p = p0 + tid;
        svx[tid] = (int)points[p * 3 + 0];
        svy[tid] = (int)points[p * 3 + 1];
        svz[tid] = (int)points[p * 3 + 2];
    }
    __syncthreads();

    const int tx = tid & 15;    // cout group: couts [tx*8, tx*8+8)
    const int ty = tid >> 4;    // point pair: points {ty*2, ty*2+1}

    float acc0[8] = {0.f,0.f,0.f,0.f,0.f,0.f,0.f,0.f};
    float acc1[8] = {0.f,0.f,0.f,0.f,0.f,0.f,0.f,0.f};

    for (int o = 0; o < NOFF; o++) {
        const int dx = o / 9 - 1;
        const int dy = (o / 3) % 3 - 1;
        const int dz = o % 3 - 1;

        // ---- stage W[o]: 64x128 fp32 = 2048 float4, 8 per thread ----
        {
            const float4* wsrc = (const float4*)(weight + (size_t)o * CIN * COUT);
            float4* wdst = (float4*)&Ws[0][0];
            #pragma unroll
            for (int i = 0; i < 8; i++)
                wdst[tid + i * 256] = wsrc[tid + i * 256];
        }

        // ---- stage A: 32 rows x 16 float4 (gather; zero if neighbor off-grid) ----
        #pragma unroll
        for (int i = 0; i < 2; i++) {
            int idx = tid + i * 256;            // 0..511
            int row = idx >> 4;
            int q   = idx & 15;
            int nx = svx[row] + dx;
            int ny = svy[row] + dy;
            int nz = svz[row] + dz;
            float4 v = make_float4(0.f, 0.f, 0.f, 0.f);
            if ((unsigned)nx < GRIDV && (unsigned)ny < GRIDV && (unsigned)nz < GRIDV) {
                int lin = (nx * GRIDV + ny) * GRIDV + nz;
                v = ((const float4*)(g_aggF + (size_t)(b * NVOX + lin) * CIN))[q];
            }
            *((float4*)&As[row][q * 4]) = v;
        }
        __syncthreads();

        // ---- compute: 64 ci iterations, 16 FFMA each ----
        #pragma unroll 8
        for (int ci = 0; ci < CIN; ci++) {
            float4 w0 = *((const float4*)&Ws[ci][tx * 8]);
            float4 w1 = *((const float4*)&Ws[ci][tx * 8 + 4]);
            float a0 = As[ty * 2 + 0][ci];
            float a1 = As[ty * 2 + 1][ci];
            acc0[0] += a0 * w0.x; acc0[1] += a0 * w0.y;
            acc0[2] += a0 * w0.z; acc0[3] += a0 * w0.w;
            acc0[4] += a0 * w1.x; acc0[5] += a0 * w1.y;
            acc0[6] += a0 * w1.z; acc0[7] += a0 * w1.w;
            acc1[0] += a1 * w0.x; acc1[1] += a1 * w0.y;
            acc1[2] += a1 * w0.z; acc1[3] += a1 * w0.w;
            acc1[4] += a1 * w1.x; acc1[5] += a1 * w1.y;
            acc1[6] += a1 * w1.z; acc1[7] += a1 * w1.w;
        }
        __syncthreads();   // protect Ws/As before next offset's staging
    }

    // ---- epilogue: add bias, write out ----
    const int co = tx * 8;
    float bb[8];
    #pragma unroll
    for (int j = 0; j < 8; j++) bb[j] = bias[co + j];

    int pA = p0 + ty * 2;
    int pB = pA + 1;
    float* oA = out + (size_t)pA * COUT + co;
    float* oB = out + (size_t)pB * COUT + co;
    #pragma unroll
    for (int j = 0; j < 8; j++) {
        oA[j] = acc0[j] + bb[j];
        oB[j] = acc1[j] + bb[j];
    }
}

// ---------------------------------------------------------------------------
extern "C" void kernel_launch(void* const* d_in, const int* in_sizes, int n_in,
                              void* d_out, int out_size) {
    const float* points  = (const float*)d_in[0];   // (B, N, 3)
    const float* feats   = (const float*)d_in[1];   // (B, N, CIN)
    const float* weight  = (const float*)d_in[2];   // (3,3,3,CIN,COUT)
    const float* bias    = (const float*)d_in[3];   // (COUT)
    float* out = (float*)d_out;                     // (B, N, COUT)

    // 1) zero scratch
    {
        int total4 = BATCH * NVOX * CIN / 4;
        int blocks = (total4 + 255) / 256;
        zero_agg_kernel<<<blocks, 256>>>();
    }
    // 2) aggregate features per voxel
    {
        int total = BATCH * NPTS * CIN;
        int blocks = (total + 255) / 256;
        aggregate_kernel<<<blocks, 256>>>(points, feats);
    }
    // 3) conv + bias
    {
        int blocks = BATCH * NPTS / TM;   // 128
        conv_kernel<<<blocks, 256>>>(points, weight, bias, out);
    }
}

// round 4
// speedup vs baseline: 3.4465x; 3.4465x over previous
#include <cuda_runtime.h>
#include <cuda_bf16.h>
#include <cstdint>

// Problem constants
#define BATCH   2
#define NPTS    2048
#define CIN     64
#define COUT    128
#define GRIDV   12
#define NVOX    (GRIDV*GRIDV*GRIDV)   // 1728
#define NOFF    27
#define TM      32                    // points per conv block
#define NBLK    (BATCH*NPTS/TM)       // 128

// Scratch (device globals; no allocation allowed)
__device__ float g_aggF[BATCH * NVOX * CIN];
// W packed in mma.sync B-fragment layout, bf16 hi/lo:
// byte addr = o*32768 + h*16384 + kk*4096 + nc*256 + lane*8 + reg*4
__device__ __align__(16) unsigned char g_Wpk[NOFF * 32768];

// ---------------------------------------------------------------------------
// Helpers
// ---------------------------------------------------------------------------
#define CP_ASYNC16(dst_u32, src_ptr) \
    asm volatile("cp.async.cg.shared.global [%0], [%1], 16;" :: "r"(dst_u32), "l"(src_ptr))
#define CP_ASYNC_COMMIT() asm volatile("cp.async.commit_group;" ::: "memory")
#define CP_ASYNC_WAIT0()  asm volatile("cp.async.wait_group 0;" ::: "memory")

__device__ __forceinline__ uint32_t smem_u32(const void* p) {
    uint32_t a;
    asm("{ .reg .u64 t; cvta.to.shared.u64 t, %1; cvt.u32.u64 %0, t; }" : "=r"(a) : "l"(p));
    return a;
}

__device__ __forceinline__ void mma_bf16(float* c, const uint32_t* a, uint32_t b0, uint32_t b1) {
    asm volatile(
        "mma.sync.aligned.m16n8k16.row.col.f32.bf16.bf16.f32 "
        "{%0,%1,%2,%3}, {%4,%5,%6,%7}, {%8,%9}, {%0,%1,%2,%3};"
        : "+f"(c[0]), "+f"(c[1]), "+f"(c[2]), "+f"(c[3])
        : "r"(a[0]), "r"(a[1]), "r"(a[2]), "r"(a[3]), "r"(b0), "r"(b1));
}

// ---------------------------------------------------------------------------
// Kernel 1: zero agg scratch + pack W into fragment layout (bf16 hi/lo)
// ---------------------------------------------------------------------------
__global__ void prep_kernel(const float* __restrict__ weight) {
    int bid = blockIdx.x;
    if (bid < 216) {
        int t = bid * 256 + threadIdx.x;
        ((float4*)g_aggF)[t] = make_float4(0.f, 0.f, 0.f, 0.f);
    } else {
        int i = (bid - 216) * 256 + threadIdx.x;   // 0..110591
        int lane = i & 31;
        int nc   = (i >> 5) & 15;
        int kk   = (i >> 9) & 3;
        int h    = (i >> 11) & 1;
        int o    = i >> 12;                        // 0..26
        int n    = nc * 8 + (lane >> 2);
        int tig  = lane & 3;
        uint32_t pk[2];
        #pragma unroll
        for (int r = 0; r < 2; r++) {
            int k = kk * 16 + tig * 2 + r * 8;
            float w0 = weight[(o * CIN + k) * COUT + n];
            float w1 = weight[(o * CIN + k + 1) * COUT + n];
            unsigned short u0, u1;
            if (h == 0) {
                u0 = __bfloat16_as_ushort(__float2bfloat16(w0));
                u1 = __bfloat16_as_ushort(__float2bfloat16(w1));
            } else {
                float r0 = w0 - __bfloat162float(__float2bfloat16(w0));
                float r1 = w1 - __bfloat162float(__float2bfloat16(w1));
                u0 = __bfloat16_as_ushort(__float2bfloat16(r0));
                u1 = __bfloat16_as_ushort(__float2bfloat16(r1));
            }
            pk[r] = ((uint32_t)u1 << 16) | u0;
        }
        *(uint2*)(g_Wpk + (size_t)o * 32768 + h * 16384 + kk * 4096 + nc * 256 + lane * 8)
            = make_uint2(pk[0], pk[1]);
    }
}

// ---------------------------------------------------------------------------
// Kernel 2: scatter-add features into per-voxel bins
// ---------------------------------------------------------------------------
__global__ void aggregate_kernel(const float* __restrict__ points,
                                 const float* __restrict__ feats) {
    int gid = blockIdx.x * blockDim.x + threadIdx.x;
    if (gid >= BATCH * NPTS * CIN) return;
    int c = gid & (CIN - 1);
    int p = gid >> 6;
    int b = p / NPTS;
    int vx = (int)points[p * 3 + 0];
    int vy = (int)points[p * 3 + 1];
    int vz = (int)points[p * 3 + 2];
    if ((unsigned)vx >= GRIDV || (unsigned)vy >= GRIDV || (unsigned)vz >= GRIDV) return;
    int lin = (vx * GRIDV + vy) * GRIDV + vz;
    atomicAdd(&g_aggF[(b * NVOX + lin) * CIN + c], feats[gid]);
}

// ---------------------------------------------------------------------------
// Kernel 3: mma.sync conv. 128 blocks x 256 threads (8 warps).
// Tile 32 points x 128 couts. Warp (wm,wn) in 2x4: 16 rows x 32 couts.
// C register-resident across 27 offsets x 3 bf16-split passes.
// A smem row stride = 144B -> conflict-free fragment LDS.
// ---------------------------------------------------------------------------
#define AROWB 144

__global__ __launch_bounds__(256, 1)
void conv_mma_kernel(const float* __restrict__ points,
                     const float* __restrict__ bias,
                     float* __restrict__ out) {
    __shared__ __align__(16) unsigned char sW[32768];   // [Wh 16K | Wl 16K]
    __shared__ __align__(16) unsigned char sAh[TM * AROWB];
    __shared__ __align__(16) unsigned char sAl[TM * AROWB];
    __shared__ int svox[3 * TM];

    const int tid  = threadIdx.x;
    const int warp = tid >> 5;
    const int lane = tid & 31;
    const int wm   = warp >> 2;      // 0..1 : rows [wm*16, +16)
    const int wn   = warp & 3;       // 0..3 : couts [wn*32, +32)
    const int grp  = lane >> 2;      // 0..7
    const int tig  = lane & 3;       // 0..3

    const int p0 = blockIdx.x * TM;
    const int b  = p0 >> 11;         // / NPTS

    if (tid < TM) {
        int p = p0 + tid;
        svox[tid]          = (int)points[p * 3 + 0];
        svox[TM + tid]     = (int)points[p * 3 + 1];
        svox[2 * TM + tid] = (int)points[p * 3 + 2];
    }
    __syncthreads();

    // A-staging geometry: thread -> (row, 8-ci group)
    const int arow = tid >> 3;           // 0..31
    const int acig = tid & 7;            // 0..7 -> ci [acig*8, +8)
    const int avx = svox[arow], avy = svox[TM + arow], avz = svox[2 * TM + arow];
    const float* aggRowBase = g_aggF + (size_t)b * NVOX * CIN + (size_t)acig * 8;

    const uint32_t sWaddr = smem_u32(sW);

    float c[16];
    #pragma unroll
    for (int i = 0; i < 16; i++) c[i] = 0.f;

    for (int o = 0; o < NOFF; o++) {
        const int dx = o / 9 - 1;
        const int dy = (o / 3) % 3 - 1;
        const int dz = o % 3 - 1;

        // ---- async-stage packed W (32KB linear copy) ----
        {
            const unsigned char* src = g_Wpk + (size_t)o * 32768 + tid * 16;
            uint32_t dst = sWaddr + tid * 16;
            #pragma unroll
            for (int i = 0; i < 8; i++)
                CP_ASYNC16(dst + i * 4096, src + i * 4096);
            CP_ASYNC_COMMIT();
        }

        // ---- gather + split A tile ----
        {
            int nx = avx + dx, ny = avy + dy, nz = avz + dz;
            float f[8];
            if ((unsigned)nx < GRIDV && (unsigned)ny < GRIDV && (unsigned)nz < GRIDV) {
                int lin = (nx * GRIDV + ny) * GRIDV + nz;
                const float4* src = (const float4*)(aggRowBase + (size_t)lin * CIN);
                float4 v0 = src[0], v1 = src[1];
                f[0]=v0.x; f[1]=v0.y; f[2]=v0.z; f[3]=v0.w;
                f[4]=v1.x; f[5]=v1.y; f[6]=v1.z; f[7]=v1.w;
            } else {
                #pragma unroll
                for (int j = 0; j < 8; j++) f[j] = 0.f;
            }
            uint32_t hp[4], lp[4];
            #pragma unroll
            for (int q = 0; q < 4; q++) {
                __nv_bfloat16 h0 = __float2bfloat16(f[2*q]);
                __nv_bfloat16 h1 = __float2bfloat16(f[2*q+1]);
                float r0 = f[2*q]   - __bfloat162float(h0);
                float r1 = f[2*q+1] - __bfloat162float(h1);
                hp[q] = ((uint32_t)__bfloat16_as_ushort(h1) << 16) | __bfloat16_as_ushort(h0);
                lp[q] = ((uint32_t)__bfloat16_as_ushort(__float2bfloat16(r1)) << 16)
                      | __bfloat16_as_ushort(__float2bfloat16(r0));
            }
            int off = arow * AROWB + acig * 16;
            *(uint4*)(sAh + off) = make_uint4(hp[0], hp[1], hp[2], hp[3]);
            *(uint4*)(sAl + off) = make_uint4(lp[0], lp[1], lp[2], lp[3]);
        }

        CP_ASYNC_WAIT0();
        __syncthreads();

        // ---- mma: 3 passes (Ah*Wh, Ah*Wl, Al*Wh) x 4 k-steps x 4 n-frags ----
        const int abase = (wm * 16 + grp) * AROWB + tig * 4;   // byte offset of a0
        #pragma unroll
        for (int pass = 0; pass < 3; pass++) {
            const unsigned char* Ab = (pass < 2) ? sAh : sAl;
            const uint32_t Wb = sWaddr + ((pass == 1) ? 16384u : 0u);
            #pragma unroll
            for (int kk = 0; kk < 4; kk++) {
                uint32_t a[4];
                const unsigned char* ap = Ab + abase + kk * 32;
                a[0] = *(const uint32_t*)(ap);
                a[1] = *(const uint32_t*)(ap + 8 * AROWB);
                a[2] = *(const uint32_t*)(ap + 16);
                a[3] = *(const uint32_t*)(ap + 8 * AROWB + 16);
                const uint32_t bp = Wb + kk * 4096 + (wn * 4) * 256 + lane * 8;
                #pragma unroll
                for (int j = 0; j < 4; j++) {
                    uint32_t bx, by;
                    asm volatile("ld.shared.v2.u32 {%0, %1}, [%2];"
                                 : "=r"(bx), "=r"(by) : "r"(bp + j * 256));
                    mma_bf16(&c[j * 4], a, bx, by);
                }
            }
        }
        __syncthreads();
    }

    // ---- epilogue: C frags + bias -> out ----
    #pragma unroll
    for (int j = 0; j < 4; j++) {
        int col = wn * 32 + j * 8 + tig * 2;
        float2 bv = *(const float2*)(bias + col);
        int r0 = p0 + wm * 16 + grp;
        float2 o0 = make_float2(c[j*4+0] + bv.x, c[j*4+1] + bv.y);
        float2 o1 = make_float2(c[j*4+2] + bv.x, c[j*4+3] + bv.y);
        *(float2*)(out + (size_t)r0 * COUT + col)       = o0;
        *(float2*)(out + (size_t)(r0 + 8) * COUT + col) = o1;
    }
}

// ---------------------------------------------------------------------------
extern "C" void kernel_launch(void* const* d_in, const int* in_sizes, int n_in,
                              void* d_out, int out_size) {
    const float* points  = (const float*)d_in[0];   // (B, N, 3)
    const float* feats   = (const float*)d_in[1];   // (B, N, CIN)
    const float* weight  = (const float*)d_in[2];   // (3,3,3,CIN,COUT)
    const float* bias    = (const float*)d_in[3];   // (COUT)
    float* out = (float*)d_out;                     // (B, N, COUT)

    // 1) zero agg scratch + pack W into bf16 hi/lo fragment layout
    prep_kernel<<<648, 256>>>(weight);
    // 2) per-voxel feature aggregation
    aggregate_kernel<<<(BATCH * NPTS * CIN + 255) / 256, 256>>>(points, feats);
    // 3) tensor-core (HMMA) conv + bias
    conv_mma_kernel<<<NBLK, 256>>>(points, bias, out);
}

// round 5
// speedup vs baseline: 4.2377x; 1.2296x over previous
#include <cuda_runtime.h>
#include <cuda_bf16.h>
#include <cstdint>

// Problem constants
#define BATCH   2
#define NPTS    2048
#define CIN     64
#define COUT    128
#define GRIDV   12
#define NVOX    (GRIDV*GRIDV*GRIDV)   // 1728
#define NOFF    27
#define TM      32                    // points per conv block
#define NBLK    (BATCH*NPTS/TM)       // 128

// Scratch (device globals; no allocation allowed)
__device__ float g_aggF[BATCH * NVOX * CIN];
// W packed in mma.sync B-fragment layout, bf16 hi/lo:
// byte addr = o*32768 + h*16384 + kk*4096 + nc*256 + lane*8 + reg*4
__device__ __align__(16) unsigned char g_Wpk[NOFF * 32768];

// ---------------------------------------------------------------------------
// Helpers
// ---------------------------------------------------------------------------
#define CP_ASYNC16(dst_u32, src_ptr) \
    asm volatile("cp.async.cg.shared.global [%0], [%1], 16;" :: "r"(dst_u32), "l"(src_ptr))
#define CP_ASYNC_COMMIT() asm volatile("cp.async.commit_group;" ::: "memory")
#define CP_ASYNC_WAIT0()  asm volatile("cp.async.wait_group 0;" ::: "memory")

__device__ __forceinline__ uint32_t smem_u32(const void* p) {
    uint32_t a;
    asm("{ .reg .u64 t; cvta.to.shared.u64 t, %1; cvt.u32.u64 %0, t; }" : "=r"(a) : "l"(p));
    return a;
}

__device__ __forceinline__ void mma_bf16(float* c, const uint32_t* a, uint32_t b0, uint32_t b1) {
    asm volatile(
        "mma.sync.aligned.m16n8k16.row.col.f32.bf16.bf16.f32 "
        "{%0,%1,%2,%3}, {%4,%5,%6,%7}, {%8,%9}, {%0,%1,%2,%3};"
        : "+f"(c[0]), "+f"(c[1]), "+f"(c[2]), "+f"(c[3])
        : "r"(a[0]), "r"(a[1]), "r"(a[2]), "r"(a[3]), "r"(b0), "r"(b1));
}

// ---------------------------------------------------------------------------
// Kernel 1: zero agg scratch + pack W into fragment layout (bf16 hi/lo)
// ---------------------------------------------------------------------------
__global__ void prep_kernel(const float* __restrict__ weight) {
    int bid = blockIdx.x;
    if (bid < 216) {
        int t = bid * 256 + threadIdx.x;
        ((float4*)g_aggF)[t] = make_float4(0.f, 0.f, 0.f, 0.f);
    } else {
        int i = (bid - 216) * 256 + threadIdx.x;   // 0..110591
        int lane = i & 31;
        int nc   = (i >> 5) & 15;
        int kk   = (i >> 9) & 3;
        int h    = (i >> 11) & 1;
        int o    = i >> 12;                        // 0..26
        int n    = nc * 8 + (lane >> 2);
        int tig  = lane & 3;
        uint32_t pk[2];
        #pragma unroll
        for (int r = 0; r < 2; r++) {
            int k = kk * 16 + tig * 2 + r * 8;
            float w0 = weight[(o * CIN + k) * COUT + n];
            float w1 = weight[(o * CIN + k + 1) * COUT + n];
            unsigned short u0, u1;
            if (h == 0) {
                u0 = __bfloat16_as_ushort(__float2bfloat16(w0));
                u1 = __bfloat16_as_ushort(__float2bfloat16(w1));
            } else {
                float r0 = w0 - __bfloat162float(__float2bfloat16(w0));
                float r1 = w1 - __bfloat162float(__float2bfloat16(w1));
                u0 = __bfloat16_as_ushort(__float2bfloat16(r0));
                u1 = __bfloat16_as_ushort(__float2bfloat16(r1));
            }
            pk[r] = ((uint32_t)u1 << 16) | u0;
        }
        *(uint2*)(g_Wpk + (size_t)o * 32768 + h * 16384 + kk * 4096 + nc * 256 + lane * 8)
            = make_uint2(pk[0], pk[1]);
    }
}

// ---------------------------------------------------------------------------
// Kernel 2: scatter-add features into per-voxel bins
// ---------------------------------------------------------------------------
__global__ void aggregate_kernel(const float* __restrict__ points,
                                 const float* __restrict__ feats) {
    int gid = blockIdx.x * blockDim.x + threadIdx.x;
    if (gid >= BATCH * NPTS * CIN) return;
    int c = gid & (CIN - 1);
    int p = gid >> 6;
    int b = p / NPTS;
    int vx = (int)points[p * 3 + 0];
    int vy = (int)points[p * 3 + 1];
    int vz = (int)points[p * 3 + 2];
    if ((unsigned)vx >= GRIDV || (unsigned)vy >= GRIDV || (unsigned)vz >= GRIDV) return;
    int lin = (vx * GRIDV + vy) * GRIDV + vz;
    atomicAdd(&g_aggF[(b * NVOX + lin) * CIN + c], feats[gid]);
}

// ---------------------------------------------------------------------------
// Kernel 3: mma.sync conv, double-buffered over offsets.
// 128 blocks x 256 threads (8 warps). Tile 32 points x 128 couts.
// Warp (wm,wn) in 2x4: 16 rows x 32 couts. C register-resident.
// Dynamic smem:
//   [0, 64K)          sW[2][32768]   (Wh 16K | Wl 16K per buffer)
//   [64K, +9216)      sAh[2][32*144]
//   [+9216, +9216)    sAl[2][32*144]
//   [.., +384)        svox
// ---------------------------------------------------------------------------
#define AROWB  144
#define ABUF   (TM * AROWB)            // 4608
#define SMO_W  0
#define SMO_AH 65536
#define SMO_AL (SMO_AH + 2 * ABUF)
#define SMO_VOX (SMO_AL + 2 * ABUF)
#define SMEM_TOTAL (SMO_VOX + 512)     // 84480

__global__ __launch_bounds__(256, 1)
void conv_mma_kernel(const float* __restrict__ points,
                     const float* __restrict__ bias,
                     float* __restrict__ out) {
    extern __shared__ __align__(16) unsigned char smem[];
    unsigned char* sW  = smem + SMO_W;
    unsigned char* sAh = smem + SMO_AH;
    unsigned char* sAl = smem + SMO_AL;
    int* svox = (int*)(smem + SMO_VOX);

    const int tid  = threadIdx.x;
    const int warp = tid >> 5;
    const int lane = tid & 31;
    const int wm   = warp >> 2;      // 0..1 : rows [wm*16, +16)
    const int wn   = warp & 3;       // 0..3 : couts [wn*32, +32)
    const int grp  = lane >> 2;      // 0..7
    const int tig  = lane & 3;       // 0..3

    const int p0 = blockIdx.x * TM;
    const int b  = p0 >> 11;         // / NPTS

    if (tid < TM) {
        int p = p0 + tid;
        svox[tid]          = (int)points[p * 3 + 0];
        svox[TM + tid]     = (int)points[p * 3 + 1];
        svox[2 * TM + tid] = (int)points[p * 3 + 2];
    }
    __syncthreads();

    // A-staging geometry: thread -> (row, 8-ci group)
    const int arow = tid >> 3;           // 0..31
    const int acig = tid & 7;            // 0..7 -> ci [acig*8, +8)
    const int avx = svox[arow], avy = svox[TM + arow], avz = svox[2 * TM + arow];
    const float* aggRowBase = g_aggF + (size_t)b * NVOX * CIN + (size_t)acig * 8;

    const uint32_t sWaddr = smem_u32(sW);
    const int aoff = arow * AROWB + acig * 16;

    // gather A for offset o into registers (8 floats)
    auto gatherA = [&](int o, float* f) {
        int dx = o / 9 - 1, dy = (o / 3) % 3 - 1, dz = o % 3 - 1;
        int nx = avx + dx, ny = avy + dy, nz = avz + dz;
        if ((unsigned)nx < GRIDV && (unsigned)ny < GRIDV && (unsigned)nz < GRIDV) {
            int lin = (nx * GRIDV + ny) * GRIDV + nz;
            const float4* src = (const float4*)(aggRowBase + (size_t)lin * CIN);
            float4 v0 = src[0], v1 = src[1];
            f[0]=v0.x; f[1]=v0.y; f[2]=v0.z; f[3]=v0.w;
            f[4]=v1.x; f[5]=v1.y; f[6]=v1.z; f[7]=v1.w;
        } else {
            #pragma unroll
            for (int j = 0; j < 8; j++) f[j] = 0.f;
        }
    };
    // split + store A registers into buffer bi
    auto storeA = [&](int bi, const float* f) {
        uint32_t hp[4], lp[4];
        #pragma unroll
        for (int q = 0; q < 4; q++) {
            __nv_bfloat16 h0 = __float2bfloat16(f[2*q]);
            __nv_bfloat16 h1 = __float2bfloat16(f[2*q+1]);
            float r0 = f[2*q]   - __bfloat162float(h0);
            float r1 = f[2*q+1] - __bfloat162float(h1);
            hp[q] = ((uint32_t)__bfloat16_as_ushort(h1) << 16) | __bfloat16_as_ushort(h0);
            lp[q] = ((uint32_t)__bfloat16_as_ushort(__float2bfloat16(r1)) << 16)
                  | __bfloat16_as_ushort(__float2bfloat16(r0));
        }
        *(uint4*)(sAh + bi * ABUF + aoff) = make_uint4(hp[0], hp[1], hp[2], hp[3]);
        *(uint4*)(sAl + bi * ABUF + aoff) = make_uint4(lp[0], lp[1], lp[2], lp[3]);
    };
    // issue cp.async for W of offset o into buffer bi
    auto issueW = [&](int o, int bi) {
        const unsigned char* src = g_Wpk + (size_t)o * 32768 + tid * 16;
        uint32_t dst = sWaddr + (uint32_t)bi * 32768u + tid * 16;
        #pragma unroll
        for (int i = 0; i < 8; i++)
            CP_ASYNC16(dst + i * 4096, src + i * 4096);
        CP_ASYNC_COMMIT();
    };

    float c[16];
    #pragma unroll
    for (int i = 0; i < 16; i++) c[i] = 0.f;

    // ---- prologue: stage W0 + A0 ----
    issueW(0, 0);
    {
        float f[8];
        gatherA(0, f);
        storeA(0, f);
    }
    CP_ASYNC_WAIT0();
    __syncthreads();

    const int abase = (wm * 16 + grp) * AROWB + tig * 4;   // byte offset of a0

    for (int o = 0; o < NOFF; o++) {
        const int cur = o & 1;
        const int nxt = cur ^ 1;
        const bool more = (o + 1 < NOFF);

        // ---- prefetch next offset's W + A while doing MMA(o) ----
        float fA[8];
        if (more) {
            issueW(o + 1, nxt);
            gatherA(o + 1, fA);   // LDGs in flight during MMA below
        }

        // ---- mma: 3 passes (Ah*Wh, Ah*Wl, Al*Wh) x 4 k-steps x 4 n-frags ----
        const unsigned char* AhB = sAh + cur * ABUF;
        const unsigned char* AlB = sAl + cur * ABUF;
        const uint32_t WbB = sWaddr + (uint32_t)cur * 32768u;
        #pragma unroll
        for (int pass = 0; pass < 3; pass++) {
            const unsigned char* Ab = (pass < 2) ? AhB : AlB;
            const uint32_t Wb = WbB + ((pass == 1) ? 16384u : 0u);
            #pragma unroll
            for (int kk = 0; kk < 4; kk++) {
                uint32_t a[4];
                const unsigned char* ap = Ab + abase + kk * 32;
                a[0] = *(const uint32_t*)(ap);
                a[1] = *(const uint32_t*)(ap + 8 * AROWB);
                a[2] = *(const uint32_t*)(ap + 16);
                a[3] = *(const uint32_t*)(ap + 8 * AROWB + 16);
                const uint32_t bp = Wb + kk * 4096 + (wn * 4) * 256 + lane * 8;
                #pragma unroll
                for (int j = 0; j < 4; j++) {
                    uint32_t bx, by;
                    asm volatile("ld.shared.v2.u32 {%0, %1}, [%2];"
                                 : "=r"(bx), "=r"(by) : "r"(bp + j * 256));
                    mma_bf16(&c[j * 4], a, bx, by);
                }
            }
        }

        if (more) {
            storeA(nxt, fA);
            CP_ASYNC_WAIT0();
        }
        __syncthreads();
    }

    // ---- epilogue: C frags + bias -> out ----
    #pragma unroll
    for (int j = 0; j < 4; j++) {
        int col = wn * 32 + j * 8 + tig * 2;
        float2 bv = *(const float2*)(bias + col);
        int r0 = p0 + wm * 16 + grp;
        float2 o0 = make_float2(c[j*4+0] + bv.x, c[j*4+1] + bv.y);
        float2 o1 = make_float2(c[j*4+2] + bv.x, c[j*4+3] + bv.y);
        *(float2*)(out + (size_t)r0 * COUT + col)       = o0;
        *(float2*)(out + (size_t)(r0 + 8) * COUT + col) = o1;
    }
}

// ---------------------------------------------------------------------------
extern "C" void kernel_launch(void* const* d_in, const int* in_sizes, int n_in,
                              void* d_out, int out_size) {
    const float* points  = (const float*)d_in[0];   // (B, N, 3)
    const float* feats   = (const float*)d_in[1];   // (B, N, CIN)
    const float* weight  = (const float*)d_in[2];   // (3,3,3,CIN,COUT)
    const float* bias    = (const float*)d_in[3];   // (COUT)
    float* out = (float*)d_out;                     // (B, N, COUT)

    cudaFuncSetAttribute(conv_mma_kernel,
                         cudaFuncAttributeMaxDynamicSharedMemorySize, SMEM_TOTAL);

    // 1) zero agg scratch + pack W into bf16 hi/lo fragment layout
    prep_kernel<<<648, 256>>>(weight);
    // 2) per-voxel feature aggregation
    aggregate_kernel<<<(BATCH * NPTS * CIN + 255) / 256, 256>>>(points, feats);
    // 3) tensor-core (HMMA) conv + bias, double-buffered
    conv_mma_kernel<<<NBLK, 256, SMEM_TOTAL>>>(points, bias, out);
}